// round 1
// baseline (speedup 1.0000x reference)
#include <cuda_runtime.h>
#include <math.h>

#define NTOK 2048
#define CDIM 768
#define HDIM 3072
#define NE 8

#define BM 128
#define BN 64
#define BK 16

// -------- scratch (__device__ globals; no allocation allowed) --------
__device__ int   g_cnt[NE];                       // tokens per expert
__device__ int   g_tok[NE * NTOK];                // token id per list slot
__device__ float g_p  [NE * NTOK];                // routing weight per slot
__device__ float g_h  [(size_t)NE * NTOK * HDIM]; // gelu(x @ Wfc_e), 201MB

__device__ __forceinline__ float gelu_tanh(float v) {
    float c = 0.7978845608028654f;
    return 0.5f * v * (1.0f + tanhf(c * (v + 0.044715f * v * v * v)));
}

// -------- kernel 0: zero counts + output --------
__global__ void zero_kernel(float* out, int n) {
    int i = blockIdx.x * blockDim.x + threadIdx.x;
    if (i < NE) g_cnt[i] = 0;
    for (; i < n; i += gridDim.x * blockDim.x) out[i] = 0.0f;
}

// -------- kernel 1: router (1 warp per token) --------
__global__ void router_kernel(const float* __restrict__ x,
                              const float* __restrict__ wg) {
    int warp = (blockIdx.x * blockDim.x + threadIdx.x) >> 5;
    int lane = threadIdx.x & 31;
    if (warp >= NTOK) return;
    const float* xr = x + (size_t)warp * CDIM;

    float acc[NE];
#pragma unroll
    for (int e = 0; e < NE; e++) acc[e] = 0.0f;

    for (int c = lane; c < CDIM; c += 32) {
        float xv = xr[c];
        const float4* w4 = (const float4*)(wg + (size_t)c * NE);
        float4 a = w4[0], b = w4[1];
        acc[0] += xv * a.x; acc[1] += xv * a.y;
        acc[2] += xv * a.z; acc[3] += xv * a.w;
        acc[4] += xv * b.x; acc[5] += xv * b.y;
        acc[6] += xv * b.z; acc[7] += xv * b.w;
    }
#pragma unroll
    for (int e = 0; e < NE; e++)
        for (int off = 16; off; off >>= 1)
            acc[e] += __shfl_xor_sync(0xffffffffu, acc[e], off);

    if (lane == 0) {
        int   i0 = 0; float l0 = acc[0];
        for (int e = 1; e < NE; e++) if (acc[e] > l0) { l0 = acc[e]; i0 = e; }
        int   i1 = -1; float l1 = -1e30f;
        for (int e = 0; e < NE; e++)
            if (e != i0 && acc[e] > l1) { l1 = acc[e]; i1 = e; }
        // renormalized top-2 softmax == 2-way softmax over the two logits
        float r  = expf(l1 - l0);
        float p0 = 1.0f / (1.0f + r);
        float p1 = r / (1.0f + r);
        int pos0 = atomicAdd(&g_cnt[i0], 1);
        g_tok[i0 * NTOK + pos0] = warp; g_p[i0 * NTOK + pos0] = p0;
        int pos1 = atomicAdd(&g_cnt[i1], 1);
        g_tok[i1 * NTOK + pos1] = warp; g_p[i1 * NTOK + pos1] = p1;
    }
}

// -------- kernel 2: per-expert gathered SGEMM + GELU --------
// h[row, n] = gelu( sum_c x[tok(row), c] * w_fc[(c*H + n)*8 + e] )
__global__ __launch_bounds__(256) void gemm1_kernel(const float* __restrict__ x,
                                                    const float* __restrict__ wfc) {
    int e   = blockIdx.z;
    int cnt = g_cnt[e];
    int m0  = blockIdx.x * BM;
    if (m0 >= cnt) return;
    int n0  = blockIdx.y * BN;

    __shared__ float As[BK * BM];
    __shared__ float Bs[BK * BN];

    int tid = threadIdx.x;
    int tx  = tid & 15;       // 16 cols of 4
    int ty  = tid >> 4;       // 16 rows of 8

    // cache gathered token ids for the 2 A-rows this thread loads
    int tok_l[2];
#pragma unroll
    for (int l = 0; l < 2; l++) {
        int m   = (tid + l * 256) >> 2;
        int row = m0 + m;
        tok_l[l] = (row < cnt) ? g_tok[e * NTOK + row] : -1;
    }

    float acc[8][4];
#pragma unroll
    for (int i = 0; i < 8; i++)
#pragma unroll
        for (int j = 0; j < 4; j++) acc[i][j] = 0.0f;

    for (int t = 0; t < CDIM; t += BK) {
#pragma unroll
        for (int l = 0; l < 2; l++) {
            int lin = tid + l * 256;
            int m   = lin >> 2;
            int kq  = (lin & 3) << 2;
            float4 v = make_float4(0.f, 0.f, 0.f, 0.f);
            if (tok_l[l] >= 0)
                v = *(const float4*)(x + (size_t)tok_l[l] * CDIM + t + kq);
            As[(kq + 0) * BM + m] = v.x;
            As[(kq + 1) * BM + m] = v.y;
            As[(kq + 2) * BM + m] = v.z;
            As[(kq + 3) * BM + m] = v.w;
        }
#pragma unroll
        for (int l = 0; l < 4; l++) {
            int lin = tid + l * 256;
            int k   = lin >> 6;
            int n   = lin & 63;
            Bs[k * BN + n] = wfc[((size_t)(t + k) * HDIM + n0 + n) * NE + e];
        }
        __syncthreads();
#pragma unroll
        for (int kk = 0; kk < BK; kk++) {
            float a[8], b[4];
#pragma unroll
            for (int i = 0; i < 8; i++) a[i] = As[kk * BM + ty * 8 + i];
#pragma unroll
            for (int j = 0; j < 4; j++) b[j] = Bs[kk * BN + tx * 4 + j];
#pragma unroll
            for (int i = 0; i < 8; i++)
#pragma unroll
                for (int j = 0; j < 4; j++) acc[i][j] += a[i] * b[j];
        }
        __syncthreads();
    }

#pragma unroll
    for (int i = 0; i < 8; i++) {
        int row = m0 + ty * 8 + i;
        float4 v;
        v.x = gelu_tanh(acc[i][0]);
        v.y = gelu_tanh(acc[i][1]);
        v.z = gelu_tanh(acc[i][2]);
        v.w = gelu_tanh(acc[i][3]);
        *(float4*)(g_h + ((size_t)e * NTOK + row) * HDIM + n0 + tx * 4) = v;
    }
}

// -------- kernel 3: per-expert SGEMM over H + weighted atomic combine --------
// out[tok(row), n] += p(row) * sum_h g_h[row, h] * w_proj[(h*C + n)*8 + e]
__global__ __launch_bounds__(256) void gemm2_kernel(const float* __restrict__ wproj,
                                                    float* __restrict__ out) {
    int e   = blockIdx.z;
    int cnt = g_cnt[e];
    int m0  = blockIdx.x * BM;
    if (m0 >= cnt) return;
    int n0  = blockIdx.y * BN;

    __shared__ float As[BK * BM];
    __shared__ float Bs[BK * BN];

    int tid = threadIdx.x;
    int tx  = tid & 15;
    int ty  = tid >> 4;

    const float* hbase = g_h + (size_t)e * NTOK * HDIM;

    float acc[8][4];
#pragma unroll
    for (int i = 0; i < 8; i++)
#pragma unroll
        for (int j = 0; j < 4; j++) acc[i][j] = 0.0f;

    for (int t = 0; t < HDIM; t += BK) {
#pragma unroll
        for (int l = 0; l < 2; l++) {
            int lin = tid + l * 256;
            int m   = lin >> 2;
            int kq  = (lin & 3) << 2;
            float4 v = *(const float4*)(hbase + (size_t)(m0 + m) * HDIM + t + kq);
            As[(kq + 0) * BM + m] = v.x;
            As[(kq + 1) * BM + m] = v.y;
            As[(kq + 2) * BM + m] = v.z;
            As[(kq + 3) * BM + m] = v.w;
        }
#pragma unroll
        for (int l = 0; l < 4; l++) {
            int lin = tid + l * 256;
            int k   = lin >> 6;
            int n   = lin & 63;
            Bs[k * BN + n] = wproj[((size_t)(t + k) * CDIM + n0 + n) * NE + e];
        }
        __syncthreads();
#pragma unroll
        for (int kk = 0; kk < BK; kk++) {
            float a[8], b[4];
#pragma unroll
            for (int i = 0; i < 8; i++) a[i] = As[kk * BM + ty * 8 + i];
#pragma unroll
            for (int j = 0; j < 4; j++) b[j] = Bs[kk * BN + tx * 4 + j];
#pragma unroll
            for (int i = 0; i < 8; i++)
#pragma unroll
                for (int j = 0; j < 4; j++) acc[i][j] += a[i] * b[j];
        }
        __syncthreads();
    }

#pragma unroll
    for (int i = 0; i < 8; i++) {
        int row = m0 + ty * 8 + i;
        if (row < cnt) {
            int   tok = g_tok[e * NTOK + row];
            float p   = g_p[e * NTOK + row];
            float* orow = out + (size_t)tok * CDIM + n0 + tx * 4;
#pragma unroll
            for (int j = 0; j < 4; j++) atomicAdd(orow + j, p * acc[i][j]);
        }
    }
}

extern "C" void kernel_launch(void* const* d_in, const int* in_sizes, int n_in,
                              void* d_out, int out_size) {
    const float* x     = (const float*)d_in[0]; // (2,1024,768)
    const float* w_fc  = (const float*)d_in[1]; // (768, 3072*8)
    const float* w_proj= (const float*)d_in[2]; // (3072*8, 768)
    const float* w_gate= (const float*)d_in[3]; // (768, 8)
    float* out = (float*)d_out;

    zero_kernel<<<1024, 256>>>(out, NTOK * CDIM);
    router_kernel<<<NTOK / 8, 256>>>(x, w_gate);

    dim3 g1(NTOK / BM, HDIM / BN, NE);  // (16, 48, 8)
    gemm1_kernel<<<g1, 256>>>(x, w_fc);

    dim3 g2(NTOK / BM, CDIM / BN, NE);  // (16, 12, 8)
    gemm2_kernel<<<g2, 256>>>(w_proj, out);
}

// round 3
// speedup vs baseline: 2.0729x; 2.0729x over previous
#include <cuda_runtime.h>
#include <cuda_bf16.h>
#include <math.h>
#include <stdint.h>

#define NTOK 2048
#define CDIM 768
#define HDIM 3072
#define NE   8

// ---------------- scratch ----------------
__device__ __align__(1024) __nv_bfloat16 g_xg_hi[NE * NTOK * CDIM];
__device__ __align__(1024) __nv_bfloat16 g_xg_lo[NE * NTOK * CDIM];
__device__ __align__(1024) __nv_bfloat16 g_wfc_hi[NE * HDIM * CDIM];
__device__ __align__(1024) __nv_bfloat16 g_wfc_lo[NE * HDIM * CDIM];
__device__ __align__(1024) __nv_bfloat16 g_wp_hi[NE * CDIM * HDIM];
__device__ __align__(1024) __nv_bfloat16 g_wp_lo[NE * CDIM * HDIM];
__device__ __align__(1024) __nv_bfloat16 g_h_hi[(size_t)NE * NTOK * HDIM];
__device__ __align__(1024) __nv_bfloat16 g_h_lo[(size_t)NE * NTOK * HDIM];
__device__ int   g_cnt[NE];
__device__ int   g_tok[NE * NTOK];
__device__ float g_p[NE * NTOK];

// ---------------- helpers ----------------
__device__ __forceinline__ uint32_t smem_u32(const void* p) {
    uint32_t a;
    asm("{ .reg .u64 t; cvta.to.shared.u64 t, %1; cvt.u32.u64 %0, t; }" : "=r"(a) : "l"(p));
    return a;
}
__device__ __forceinline__ void cpa16(uint32_t dst, const void* src) {
    asm volatile("cp.async.cg.shared.global [%0], [%1], 16;" :: "r"(dst), "l"(src));
}
#define CP_COMMIT() asm volatile("cp.async.commit_group;" ::: "memory")
#define CP_WAIT(n)  asm volatile("cp.async.wait_group %0;" :: "n"(n) : "memory")

__device__ __forceinline__ void ldsm4(uint32_t* r, uint32_t addr) {
    asm volatile("ldmatrix.sync.aligned.m8n8.x4.shared.b16 {%0,%1,%2,%3}, [%4];"
        : "=r"(r[0]), "=r"(r[1]), "=r"(r[2]), "=r"(r[3]) : "r"(addr));
}
__device__ __forceinline__ void mma16816(float* d, const uint32_t* a,
                                         uint32_t b0, uint32_t b1) {
    asm volatile("mma.sync.aligned.m16n8k16.row.col.f32.bf16.bf16.f32 "
        "{%0,%1,%2,%3}, {%4,%5,%6,%7}, {%8,%9}, {%0,%1,%2,%3};"
        : "+f"(d[0]), "+f"(d[1]), "+f"(d[2]), "+f"(d[3])
        : "r"(a[0]), "r"(a[1]), "r"(a[2]), "r"(a[3]), "r"(b0), "r"(b1));
}
__device__ __forceinline__ float gelu_tanh(float v) {
    float c = 0.7978845608028654f;
    return 0.5f * v * (1.0f + tanhf(c * (v + 0.044715f * v * v * v)));
}

// ---------------- kernel: zero ----------------
__global__ void zero_kernel(float* out, int n) {
    int i = blockIdx.x * blockDim.x + threadIdx.x;
    if (i < NE) g_cnt[i] = 0;
    for (; i < n; i += gridDim.x * blockDim.x) out[i] = 0.0f;
}

// ---------------- kernel: router ----------------
__global__ void router_kernel(const float* __restrict__ x, const float* __restrict__ wg) {
    int warp = (blockIdx.x * blockDim.x + threadIdx.x) >> 5;
    int lane = threadIdx.x & 31;
    if (warp >= NTOK) return;
    const float* xr = x + (size_t)warp * CDIM;
    float acc[NE];
#pragma unroll
    for (int e = 0; e < NE; e++) acc[e] = 0.0f;
    for (int c = lane; c < CDIM; c += 32) {
        float xv = xr[c];
        const float4* w4 = (const float4*)(wg + (size_t)c * NE);
        float4 a = w4[0], b = w4[1];
        acc[0] += xv * a.x; acc[1] += xv * a.y; acc[2] += xv * a.z; acc[3] += xv * a.w;
        acc[4] += xv * b.x; acc[5] += xv * b.y; acc[6] += xv * b.z; acc[7] += xv * b.w;
    }
#pragma unroll
    for (int e = 0; e < NE; e++)
        for (int off = 16; off; off >>= 1)
            acc[e] += __shfl_xor_sync(0xffffffffu, acc[e], off);
    if (lane == 0) {
        int i0 = 0; float l0 = acc[0];
        for (int e = 1; e < NE; e++) if (acc[e] > l0) { l0 = acc[e]; i0 = e; }
        int i1 = -1; float l1 = -1e30f;
        for (int e = 0; e < NE; e++) if (e != i0 && acc[e] > l1) { l1 = acc[e]; i1 = e; }
        float r  = expf(l1 - l0);
        float p0 = 1.0f / (1.0f + r);
        float p1 = r / (1.0f + r);
        int pos0 = atomicAdd(&g_cnt[i0], 1);
        g_tok[i0 * NTOK + pos0] = warp; g_p[i0 * NTOK + pos0] = p0;
        int pos1 = atomicAdd(&g_cnt[i1], 1);
        g_tok[i1 * NTOK + pos1] = warp; g_p[i1 * NTOK + pos1] = p1;
    }
}

// ---------------- kernel: gather x -> per-expert bf16 hi/lo slabs (zero-fill) ------
__global__ __launch_bounds__(256) void gather_x(const float* __restrict__ x) {
    int g = blockIdx.x * 8 + (threadIdx.x >> 5);
    int lane = threadIdx.x & 31;
    int e = g >> 11, row = g & 2047;
    size_t dst = (size_t)g * CDIM;
    if (row >= g_cnt[e]) {
        uint4 z = make_uint4(0, 0, 0, 0);
        for (int c = lane * 8; c < CDIM; c += 256) {
            *(uint4*)(g_xg_hi + dst + c) = z;
            *(uint4*)(g_xg_lo + dst + c) = z;
        }
        return;
    }
    int tok = g_tok[g];
    const float* xr = x + (size_t)tok * CDIM;
    for (int c = lane; c < CDIM; c += 32) {
        float v = xr[c];
        __nv_bfloat16 h = __float2bfloat16(v);
        g_xg_hi[dst + c] = h;
        g_xg_lo[dst + c] = __float2bfloat16(v - __bfloat162float(h));
    }
}

// ---------------- kernel: repack weights ----------------
// src[(k*NT + n)*8 + e]  ->  dst[(e*NT + n)*KT + k]   (bf16 hi/lo)
__global__ __launch_bounds__(256) void repack_w(const float* __restrict__ src,
                                                __nv_bfloat16* __restrict__ hi,
                                                __nv_bfloat16* __restrict__ lo,
                                                int KT, int NT) {
    __shared__ __align__(16) unsigned short st[16][264];
    int n  = blockIdx.y;
    int k0 = blockIdx.x * 256;
    int t  = threadIdx.x;
    int k  = k0 + t;
    const float4* s4 = (const float4*)(src + ((size_t)k * NT + n) * 8);
    float4 a = s4[0], b = s4[1];
    float v[8] = {a.x, a.y, a.z, a.w, b.x, b.y, b.z, b.w};
#pragma unroll
    for (int e = 0; e < 8; e++) {
        __nv_bfloat16 h = __float2bfloat16(v[e]);
        __nv_bfloat16 l = __float2bfloat16(v[e] - __bfloat162float(h));
        st[2 * e][t]     = __bfloat16_as_ushort(h);
        st[2 * e + 1][t] = __bfloat16_as_ushort(l);
    }
    __syncthreads();
    int p = t >> 4, i = t & 15;
    int e = p >> 1;
    __nv_bfloat16* dst = (p & 1) ? lo : hi;
    size_t off = ((size_t)e * NT + n) * KT + k0 + i * 16;
    uint4* d4 = (uint4*)(dst + off);
    const uint4* s = (const uint4*)&st[p][i * 16];
    d4[0] = s[0];
    d4[1] = s[1];
}

// ---------------- tensor-core GEMM (mma.sync bf16 split-3, cp.async pipeline) ------
// PHASE 1: D = Xg @ Wfc^T, gelu -> g_h hi/lo        (WM=4 -> BM=128)
// PHASE 2: D = H  @ Wp^T,  * p -> atomicAdd(out)    (WM=2 -> BM=64)
template <int WM, int PHASE>
__global__ __launch_bounds__(256, 1) void gemm_ws(
    const __nv_bfloat16* __restrict__ Ah, const __nv_bfloat16* __restrict__ Al,
    const __nv_bfloat16* __restrict__ Bh, const __nv_bfloat16* __restrict__ Bl,
    int Kdim, int Ndim, float* __restrict__ out) {

    constexpr int BM  = WM * 32;      // 2 warps in M
    constexpr int BN  = 128;          // 4 warps in N, 32 cols each
    constexpr int BK  = 32;
    constexpr int SA  = BK + 8;       // halves per smem row (80B)
    constexpr int NST = 3;
    constexpr int ASZ = BM * SA;      // halves
    constexpr int BSZ = BN * SA;
    constexpr int STG = 2 * ASZ + 2 * BSZ;

    int e   = blockIdx.z;
    int cnt = g_cnt[e];
    int m0  = blockIdx.x * BM;
    if (m0 >= cnt) return;
    int n0  = blockIdx.y * BN;

    extern __shared__ __nv_bfloat16 sm[];
    uint32_t sbase = smem_u32(sm);

    const __nv_bfloat16* Ah_p = Ah + ((size_t)e * NTOK + m0) * Kdim;
    const __nv_bfloat16* Al_p = Al + ((size_t)e * NTOK + m0) * Kdim;
    const __nv_bfloat16* Bh_p = Bh + ((size_t)e * Ndim + n0) * Kdim;
    const __nv_bfloat16* Bl_p = Bl + ((size_t)e * Ndim + n0) * Kdim;

    int tid  = threadIdx.x;
    int lane = tid & 31;
    int wid  = tid >> 5;
    int wm   = wid & 1;
    int wn   = wid >> 1;
    int mb   = wm * WM * 16;
    int nb   = wn * 32;

    auto issue = [&](int stage, int kb) {
        int k0 = kb * BK;
        uint32_t s0 = sbase + stage * STG * 2;
#pragma unroll
        for (int t = tid; t < BM * 4; t += 256) {
            int r = t >> 2, c = t & 3;
            uint32_t d = s0 + (r * SA + c * 8) * 2;
            const __nv_bfloat16* sh = Ah_p + (size_t)r * Kdim + k0 + c * 8;
            const __nv_bfloat16* sl = Al_p + (size_t)r * Kdim + k0 + c * 8;
            cpa16(d, sh);
            cpa16(d + ASZ * 2, sl);
        }
#pragma unroll
        for (int t = tid; t < BN * 4; t += 256) {
            int r = t >> 2, c = t & 3;
            uint32_t d = s0 + (2 * ASZ + r * SA + c * 8) * 2;
            const __nv_bfloat16* sh = Bh_p + (size_t)r * Kdim + k0 + c * 8;
            const __nv_bfloat16* sl = Bl_p + (size_t)r * Kdim + k0 + c * 8;
            cpa16(d, sh);
            cpa16(d + BSZ * 2, sl);
        }
        CP_COMMIT();
    };

    float acc[WM][4][4];
#pragma unroll
    for (int i = 0; i < WM; i++)
#pragma unroll
        for (int j = 0; j < 4; j++)
#pragma unroll
            for (int q = 0; q < 4; q++) acc[i][j][q] = 0.0f;

    // ldmatrix lane addressing
    int q8   = lane >> 3;
    int rr   = lane & 7;
    int lrow = rr + (q8 & 1) * 8;
    int lcol = (q8 >> 1) * 8;

    auto compute = [&](int stage) {
        uint32_t s0 = sbase + stage * STG * 2;
#pragma unroll
        for (int kk = 0; kk < BK; kk += 16) {
            uint32_t ah[WM][4], al[WM][4];
#pragma unroll
            for (int mi = 0; mi < WM; mi++) {
                uint32_t addr = s0 + ((mb + mi * 16 + lrow) * SA + kk + lcol) * 2;
                ldsm4(ah[mi], addr);
                ldsm4(al[mi], addr + ASZ * 2);
            }
#pragma unroll
            for (int np = 0; np < 2; np++) {
                uint32_t bh[4], bl[4];
                uint32_t addr = s0 + (2 * ASZ + (nb + np * 16 + lrow) * SA + kk + lcol) * 2;
                ldsm4(bh, addr);
                ldsm4(bl, addr + BSZ * 2);
#pragma unroll
                for (int mi = 0; mi < WM; mi++) {
#pragma unroll
                    for (int s = 0; s < 2; s++) {
                        float* d = acc[mi][np * 2 + s];
                        mma16816(d, ah[mi], bh[s], bh[s + 2]);
                        mma16816(d, ah[mi], bl[s], bl[s + 2]);
                        mma16816(d, al[mi], bh[s], bh[s + 2]);
                    }
                }
            }
        }
    };

    int KIT = Kdim / BK;
#pragma unroll
    for (int s = 0; s < NST - 1; s++) issue(s, s);
#pragma unroll 1
    for (int it = 0; it < KIT; it++) {
        CP_WAIT(NST - 2);
        __syncthreads();
        int nk = it + NST - 1;
        if (nk < KIT) issue(nk % NST, nk);
        compute(it % NST);
    }

    // ---------------- epilogue ----------------
    int fr = lane >> 2;           // 0..7
    int fc = (lane & 3) * 2;

    if (PHASE == 1) {
#pragma unroll
        for (int mi = 0; mi < WM; mi++) {
#pragma unroll
            for (int half = 0; half < 2; half++) {
                int r = m0 + mb + mi * 16 + fr + half * 8;
                size_t base = ((size_t)e * NTOK + r) * HDIM;
#pragma unroll
                for (int ni = 0; ni < 4; ni++) {
                    int cg = n0 + nb + ni * 8 + fc;
                    float v0 = gelu_tanh(acc[mi][ni][half * 2 + 0]);
                    float v1 = gelu_tanh(acc[mi][ni][half * 2 + 1]);
                    __nv_bfloat16 h0 = __float2bfloat16(v0);
                    __nv_bfloat16 h1 = __float2bfloat16(v1);
                    __nv_bfloat16 l0 = __float2bfloat16(v0 - __bfloat162float(h0));
                    __nv_bfloat16 l1 = __float2bfloat16(v1 - __bfloat162float(h1));
                    uint32_t ph = (uint32_t)__bfloat16_as_ushort(h0) |
                                  ((uint32_t)__bfloat16_as_ushort(h1) << 16);
                    uint32_t pl = (uint32_t)__bfloat16_as_ushort(l0) |
                                  ((uint32_t)__bfloat16_as_ushort(l1) << 16);
                    *(uint32_t*)(g_h_hi + base + cg) = ph;
                    *(uint32_t*)(g_h_lo + base + cg) = pl;
                }
            }
        }
    } else {
#pragma unroll
        for (int mi = 0; mi < WM; mi++) {
#pragma unroll
            for (int half = 0; half < 2; half++) {
                int slot = m0 + mb + mi * 16 + fr + half * 8;
                if (slot < cnt) {
                    int   tok = g_tok[e * NTOK + slot];
                    float pw  = g_p[e * NTOK + slot];
                    float* orow = out + (size_t)tok * CDIM;
#pragma unroll
                    for (int ni = 0; ni < 4; ni++) {
                        int cg = n0 + nb + ni * 8 + fc;
                        atomicAdd(orow + cg,     pw * acc[mi][ni][half * 2 + 0]);
                        atomicAdd(orow + cg + 1, pw * acc[mi][ni][half * 2 + 1]);
                    }
                }
            }
        }
    }
}

// ---------------- host ----------------
extern "C" void kernel_launch(void* const* d_in, const int* in_sizes, int n_in,
                              void* d_out, int out_size) {
    const float* x      = (const float*)d_in[0];
    const float* w_fc   = (const float*)d_in[1];
    const float* w_proj = (const float*)d_in[2];
    const float* w_gate = (const float*)d_in[3];
    float* out = (float*)d_out;

    void *p_fh, *p_fl, *p_ph, *p_pl, *p_xh, *p_xl, *p_hh, *p_hl;
    cudaGetSymbolAddress(&p_fh, g_wfc_hi);
    cudaGetSymbolAddress(&p_fl, g_wfc_lo);
    cudaGetSymbolAddress(&p_ph, g_wp_hi);
    cudaGetSymbolAddress(&p_pl, g_wp_lo);
    cudaGetSymbolAddress(&p_xh, g_xg_hi);
    cudaGetSymbolAddress(&p_xl, g_xg_lo);
    cudaGetSymbolAddress(&p_hh, g_h_hi);
    cudaGetSymbolAddress(&p_hl, g_h_lo);

    constexpr int SMEM1 = 3 * (2 * 128 * 40 + 2 * 128 * 40) * 2;  // 122880
    constexpr int SMEM2 = 3 * (2 * 64 * 40 + 2 * 128 * 40) * 2;   // 92160
    cudaFuncSetAttribute(gemm_ws<4, 1>, cudaFuncAttributeMaxDynamicSharedMemorySize, SMEM1);
    cudaFuncSetAttribute(gemm_ws<2, 2>, cudaFuncAttributeMaxDynamicSharedMemorySize, SMEM2);

    zero_kernel<<<1024, 256>>>(out, NTOK * CDIM);
    router_kernel<<<NTOK / 8, 256>>>(x, w_gate);
    gather_x<<<NE * NTOK / 8, 256>>>(x);
    repack_w<<<dim3(CDIM / 256, HDIM), 256>>>(w_fc, (__nv_bfloat16*)p_fh, (__nv_bfloat16*)p_fl, CDIM, HDIM);
    repack_w<<<dim3(HDIM / 256, CDIM), 256>>>(w_proj, (__nv_bfloat16*)p_ph, (__nv_bfloat16*)p_pl, HDIM, CDIM);

    dim3 g1(NTOK / 128, HDIM / 128, NE);  // (16, 24, 8)
    gemm_ws<4, 1><<<g1, 256, SMEM1>>>((const __nv_bfloat16*)p_xh, (const __nv_bfloat16*)p_xl,
                                      (const __nv_bfloat16*)p_fh, (const __nv_bfloat16*)p_fl,
                                      CDIM, HDIM, out);
    dim3 g2(NTOK / 64, CDIM / 128, NE);   // (32, 6, 8)
    gemm_ws<2, 2><<<g2, 256, SMEM2>>>((const __nv_bfloat16*)p_hh, (const __nv_bfloat16*)p_hl,
                                      (const __nv_bfloat16*)p_ph, (const __nv_bfloat16*)p_pl,
                                      HDIM, CDIM, out);
}